// round 14
// baseline (speedup 1.0000x reference)
#include <cuda_runtime.h>
#include <cuda_bf16.h>
#include <cstdint>
#include <math.h>

// ---------------------------------------------------------------------------
// Problem constants
// ---------------------------------------------------------------------------
#define NTOK   16384          // B*L
#define DMOD   1152           // D
#define D3C    384            // D/3
#define NHEAD  16
#define DK3C   24
#define ROWS3  (NTOK * 3)     // 49152
#define SCORE_SCALE 0.1178511301977579f   // 1/sqrt(72)

#define W4SZ   (D3C * D3C)
#define WOSZ   (DMOD * DMOD)
#define WO_OFF (4 * W4SZ)
#define WT_WORDS ((WO_OFF + WOSZ) / 2)

// ---------------------------------------------------------------------------
// Scratch
// ---------------------------------------------------------------------------
__device__ __align__(16) uint32_t g_xn[NTOK * DMOD / 2];          // LN out, bf16x2
__device__ __align__(16) __nv_bfloat16 g_proj[4][ROWS3 * D3C];    // q,k,v,gate bf16
__device__ __align__(16) __nv_bfloat16 g_hout[NTOK * DMOD];       // attn out, bf16
__device__ __align__(16) uint32_t g_wt[WT_WORDS];                 // weights, bf16x2

// ---------------------------------------------------------------------------
// Helpers
// ---------------------------------------------------------------------------
__device__ __forceinline__ uint32_t pack_bf16x2(float lo, float hi) {
    uint32_t r;
    asm("cvt.rn.bf16x2.f32 %0, %1, %2;" : "=r"(r) : "f"(hi), "f"(lo));
    return r;
}
__device__ __forceinline__ uint32_t smem_u32(const void* p) {
    uint32_t a;
    asm("{ .reg .u64 t; cvta.to.shared.u64 t, %1; cvt.u32.u64 %0, t; }" : "=r"(a) : "l"(p));
    return a;
}
__device__ __forceinline__ void cp_async16(uint32_t dst, const void* src) {
    asm volatile("cp.async.cg.shared.global [%0], [%1], 16;" :: "r"(dst), "l"(src));
}
__device__ __forceinline__ void cp_commit() {
    asm volatile("cp.async.commit_group;" ::: "memory");
}
template<int N>
__device__ __forceinline__ void cp_wait() {
    asm volatile("cp.async.wait_group %0;" :: "n"(N) : "memory");
}
__device__ __forceinline__ void mma_bf16(float* d, const uint32_t* a, const uint32_t* b) {
    asm volatile(
        "mma.sync.aligned.m16n8k16.row.col.f32.bf16.bf16.f32 "
        "{%0,%1,%2,%3}, {%4,%5,%6,%7}, {%8,%9}, {%0,%1,%2,%3};"
        : "+f"(d[0]), "+f"(d[1]), "+f"(d[2]), "+f"(d[3])
        : "r"(a[0]), "r"(a[1]), "r"(a[2]), "r"(a[3]), "r"(b[0]), "r"(b[1]));
}
__device__ __forceinline__ void ldmatrix_x4(uint32_t* r, uint32_t addr) {
    asm volatile("ldmatrix.sync.aligned.m8n8.x4.shared.b16 {%0,%1,%2,%3}, [%4];"
        : "=r"(r[0]), "=r"(r[1]), "=r"(r[2]), "=r"(r[3]) : "r"(addr));
}
__device__ __forceinline__ void bf8_to_f(const uint4& u, float* f) {
    const __nv_bfloat162* p = reinterpret_cast<const __nv_bfloat162*>(&u);
    #pragma unroll
    for (int i = 0; i < 4; i++) {
        float2 v = __bfloat1622float2(p[i]);
        f[2 * i] = v.x; f[2 * i + 1] = v.y;
    }
}

// ---------------------------------------------------------------------------
// Kernel 1: LayerNorm -> bf16x2
// ---------------------------------------------------------------------------
__global__ void ln_kernel(const float* __restrict__ x,
                          const float* __restrict__ gamma,
                          const float* __restrict__ beta,
                          uint32_t* __restrict__ xn) {
    const int n = blockIdx.x;
    const int t = threadIdx.x;
    const float4* xr = reinterpret_cast<const float4*>(x + (size_t)n * DMOD);
    float4 v = xr[t];
    float s  = v.x + v.y + v.z + v.w;
    float ss = v.x * v.x + v.y * v.y + v.z * v.z + v.w * v.w;
    #pragma unroll
    for (int off = 16; off > 0; off >>= 1) {
        s  += __shfl_xor_sync(0xffffffffu, s,  off);
        ss += __shfl_xor_sync(0xffffffffu, ss, off);
    }
    __shared__ float red_s[9], red_ss[9], stat[2];
    const int warp = t >> 5, lane = t & 31;
    if (lane == 0) { red_s[warp] = s; red_ss[warp] = ss; }
    __syncthreads();
    if (t == 0) {
        float ts = 0.f, tss = 0.f;
        #pragma unroll
        for (int i = 0; i < 9; i++) { ts += red_s[i]; tss += red_ss[i]; }
        float mu  = ts * (1.0f / DMOD);
        float var = tss * (1.0f / DMOD) - mu * mu;
        stat[0] = mu; stat[1] = rsqrtf(var + 1e-6f);
    }
    __syncthreads();
    const float mu = stat[0], rstd = stat[1];
    const float4 gm = reinterpret_cast<const float4*>(gamma)[t];
    const float4 be = reinterpret_cast<const float4*>(beta)[t];
    uint2 o;
    o.x = pack_bf16x2((v.x - mu) * rstd * gm.x + be.x, (v.y - mu) * rstd * gm.y + be.y);
    o.y = pack_bf16x2((v.z - mu) * rstd * gm.z + be.z, (v.w - mu) * rstd * gm.w + be.w);
    reinterpret_cast<uint2*>(xn + (size_t)n * (DMOD / 2))[t] = o;
}

// ---------------------------------------------------------------------------
// Kernel 1b: weights fp32 -> bf16x2
// ---------------------------------------------------------------------------
__global__ void prep_w(const float* __restrict__ Wq, const float* __restrict__ Wk,
                       const float* __restrict__ Wv, const float* __restrict__ Wg,
                       const float* __restrict__ Wo) {
    for (int i = blockIdx.x * blockDim.x + threadIdx.x; i < WT_WORDS;
         i += gridDim.x * blockDim.x) {
        float lo, hi;
        if (i < WO_OFF / 2) {
            const int z = i / (W4SZ / 2), r = i % (W4SZ / 2);
            const float* W = (z == 0) ? Wq : (z == 1) ? Wk : (z == 2) ? Wv : Wg;
            lo = W[2 * r]; hi = W[2 * r + 1];
        } else {
            const int j = i - WO_OFF / 2;
            lo = Wo[2 * j]; hi = Wo[2 * j + 1];
        }
        g_wt[i] = pack_bf16x2(lo, hi);
    }
}

// ---------------------------------------------------------------------------
// bf16 mma.sync GEMM with ldmatrix.  Block 256x128, 8 warps, warp 64x64.
// K-chunk = 64, 3-stage cp.async pipeline, one barrier per 64-K.
// (unchanged from the validated 510us round-11 kernel)
// ---------------------------------------------------------------------------
struct GemmPtrs {
    const float*    bias[4];
    void*           C[4];
    const uint32_t* W[4];
    const float*    resid;
    const float*    g;
};

#define PITCH  36                 // u32 words per smem row (32 data + 4 pad)
#define LROWS  384
#define SSW    (LROWS * PITCH)    // 13824
#define NSTG   3

template<int KD, bool RES, bool OUTB>
__global__ __launch_bounds__(256)
void mma_gemm(const uint32_t* __restrict__ A, GemmPtrs gp, int Ntot) {
    constexpr int KW = KD / 2;
    constexpr int NC = KD / 64;
    extern __shared__ uint32_t sm[];

    const int tid  = threadIdx.x;
    const int wid  = tid >> 5;
    const int lane = tid & 31;
    const int g    = lane >> 2;
    const int t4   = lane & 3;
    const int wm0  = (wid >> 1) * 64;
    const int wn0  = (wid & 1) * 64;
    const int z    = blockIdx.z;

    const uint32_t* W    = gp.W[z];
    const float*    bias = gp.bias[z];
    const int bm = blockIdx.y * 256;
    const int bn = blockIdx.x * 128;

    const uint32_t smaddr = smem_u32(sm);

    uint32_t adrA[4];
    #pragma unroll
    for (int ms = 0; ms < 4; ms++) {
        const int row = wm0 + ms * 16 + (lane & 15);
        const int wof = ((lane >> 4) & 1) * 4;
        adrA[ms] = (uint32_t)(row * PITCH + wof) * 4u;
    }
    uint32_t adrB[4];
    #pragma unroll
    for (int ps = 0; ps < 4; ps++) {
        const int row = wn0 + ps * 16 + (lane & 7) + ((lane >> 4) & 1) * 8;
        const int wof = ((lane >> 3) & 1) * 4;
        adrB[ps] = (uint32_t)(256 * PITCH + row * PITCH + wof) * 4u;
    }

    auto load_stage = [&](int c, int slot) {
        const int k0 = c * 32;
        const uint32_t sb = smaddr + (uint32_t)(slot * SSW) * 4u;
        #pragma unroll
        for (int t = 0; t < 12; t++) {
            const int idx = tid + t * 256;
            const int row = idx >> 3;
            const int q   = idx & 7;
            const uint32_t* src = (row < 256)
                ? (A + (size_t)(bm + row) * KW + k0 + q * 4)
                : (W + (size_t)(bn + row - 256) * KW + k0 + q * 4);
            cp_async16(sb + (uint32_t)(row * PITCH + q * 4) * 4u, src);
        }
        cp_commit();
    };

    float acc[4][8][4];
    #pragma unroll
    for (int i = 0; i < 4; i++)
        #pragma unroll
        for (int j = 0; j < 8; j++)
            #pragma unroll
            for (int r = 0; r < 4; r++) acc[i][j][r] = 0.f;

    load_stage(0, 0);
    load_stage(1, 1);

    int cslot = 0;
    int lslot = 2;
    for (int c = 0; c < NC; c++) {
        if (c < NC - 1) cp_wait<1>(); else cp_wait<0>();
        __syncthreads();
        if (c + 2 < NC) {
            load_stage(c + 2, lslot);
            if (++lslot == NSTG) lslot = 0;
        }

        const uint32_t sbase = smaddr + (uint32_t)(cslot * SSW) * 4u;
        if (++cslot == NSTG) cslot = 0;

        #pragma unroll
        for (int u = 0; u < 4; u++) {
            const uint32_t hbase = sbase + u * 32u;
            uint32_t afr[4][4];
            #pragma unroll
            for (int ms = 0; ms < 4; ms++)
                ldmatrix_x4(afr[ms], hbase + adrA[ms]);
            #pragma unroll
            for (int ps = 0; ps < 4; ps++) {
                uint32_t bfr[4];
                ldmatrix_x4(bfr, hbase + adrB[ps]);
                #pragma unroll
                for (int ms = 0; ms < 4; ms++) {
                    mma_bf16(acc[ms][2 * ps],     afr[ms], bfr);
                    mma_bf16(acc[ms][2 * ps + 1], afr[ms], bfr + 2);
                }
            }
        }
    }

    const float gval = RES ? __ldg(gp.g) : 0.f;
    #pragma unroll
    for (int ms = 0; ms < 4; ms++) {
        const int row0 = bm + wm0 + ms * 16 + g;
        #pragma unroll
        for (int ns = 0; ns < 8; ns++) {
            const int col = bn + wn0 + ns * 8 + 2 * t4;
            const float b0 = __ldg(bias + col);
            const float b1 = __ldg(bias + col + 1);
            float o0 = acc[ms][ns][0] + b0;
            float o1 = acc[ms][ns][1] + b1;
            float o2 = acc[ms][ns][2] + b0;
            float o3 = acc[ms][ns][3] + b1;
            if (RES) {
                const float* r0 = gp.resid + (size_t)row0 * Ntot + col;
                const float* r1 = gp.resid + (size_t)(row0 + 8) * Ntot + col;
                o0 = fmaf(r0[0], gval, o0);
                o1 = fmaf(r0[1], gval, o1);
                o2 = fmaf(r1[0], gval, o2);
                o3 = fmaf(r1[1], gval, o3);
            }
            if (OUTB) {
                uint32_t* Cw = (uint32_t*)gp.C[z];
                Cw[(size_t)row0 * (Ntot / 2) + (col >> 1)]       = pack_bf16x2(o0, o1);
                Cw[(size_t)(row0 + 8) * (Ntot / 2) + (col >> 1)] = pack_bf16x2(o2, o3);
            } else {
                float* C = (float*)gp.C[z];
                *reinterpret_cast<float2*>(C + (size_t)row0 * Ntot + col)       = make_float2(o0, o1);
                *reinterpret_cast<float2*>(C + (size_t)(row0 + 8) * Ntot + col) = make_float2(o2, o3);
            }
        }
    }
}

// ---------------------------------------------------------------------------
// Attention + gate: smem-staged.  Block = 128 threads = 8 tokens x 16 heads.
// Bulk cp.async of the 4 contiguous g_proj slices (4 x 18432B = 73728B),
// then per-(token, head) compute from smem.  3 blocks/SM -> load/compute
// overlap across blocks.
// ---------------------------------------------------------------------------
#define ATOK      8                       // tokens per block
#define ASLICE    (ATOK * 3 * D3C * 2)    // bytes per tensor slice (18432)
#define ASMEM     (4 * ASLICE)            // 73728

__global__ __launch_bounds__(128)
void attn_kernel() {
    extern __shared__ uint8_t asmem[];
    const int tid = threadIdx.x;
    const int blk = blockIdx.x;
    const uint32_t sb = smem_u32(asmem);

    // Bulk load: 4 tensors x 1152 x 16B chunks, fully coalesced.
    const size_t gelem = (size_t)blk * ATOK * 3 * D3C;    // element offset of slice
    #pragma unroll
    for (int p = 0; p < 4; p++) {
        const uint8_t* src = reinterpret_cast<const uint8_t*>(&g_proj[p][gelem]);
        #pragma unroll
        for (int t = 0; t < 9; t++) {
            const int idx = tid + t * 128;                // 0..1151
            cp_async16(sb + p * ASLICE + idx * 16, src + idx * 16);
        }
    }
    cp_commit();
    cp_wait<0>();
    __syncthreads();

    const int ltok = tid >> 4;
    const int h    = tid & 15;
    // element offset within a tensor slice for (ltok, i, h, c):
    //   ltok*1152 + i*384 + h*24 + c*8   (bf16 elements; x2 for bytes)
    const uint32_t tbase = (uint32_t)(ltok * 3 * D3C + h * DK3C) * 2;

    const uint8_t* qs = asmem + 0 * ASLICE + tbase;
    const uint8_t* ks = asmem + 1 * ASLICE + tbase;
    const uint8_t* vs = asmem + 2 * ASLICE + tbase;
    const uint8_t* gs = asmem + 3 * ASLICE + tbase;
    // byte stride per group i: D3C*2 = 768; per c-chunk: 16

    float s[3][3] = {{0.f,0.f,0.f},{0.f,0.f,0.f},{0.f,0.f,0.f}};
    #pragma unroll
    for (int c = 0; c < 3; c++) {
        float qf[3][8], kf[3][8];
        #pragma unroll
        for (int i = 0; i < 3; i++) {
            bf8_to_f(*reinterpret_cast<const uint4*>(qs + i * 768 + c * 16), qf[i]);
            bf8_to_f(*reinterpret_cast<const uint4*>(ks + i * 768 + c * 16), kf[i]);
        }
        #pragma unroll
        for (int i = 0; i < 3; i++)
            #pragma unroll
            for (int j = 0; j < 3; j++) {
                float p = 0.f;
                #pragma unroll
                for (int d = 0; d < 8; d++) p = fmaf(qf[i][d], kf[j][d], p);
                s[i][j] += p;
            }
    }

    float a[3][3];
    #pragma unroll
    for (int i = 0; i < 3; i++) {
        float s0 = s[i][0] * SCORE_SCALE, s1 = s[i][1] * SCORE_SCALE, s2 = s[i][2] * SCORE_SCALE;
        float m = fmaxf(s0, fmaxf(s1, s2));
        float e0 = __expf(s0 - m), e1 = __expf(s1 - m), e2 = __expf(s2 - m);
        float inv = 1.0f / (e0 + e1 + e2);
        a[i][0] = e0 * inv; a[i][1] = e1 * inv; a[i][2] = e2 * inv;
    }

    const int n = blk * ATOK + ltok;
    const size_t obase = (size_t)n * DMOD + h * DK3C;
    #pragma unroll
    for (int c = 0; c < 3; c++) {
        float vf[3][8], gf[3][8];
        #pragma unroll
        for (int j = 0; j < 3; j++)
            bf8_to_f(*reinterpret_cast<const uint4*>(vs + j * 768 + c * 16), vf[j]);
        #pragma unroll
        for (int i = 0; i < 3; i++)
            bf8_to_f(*reinterpret_cast<const uint4*>(gs + i * 768 + c * 16), gf[i]);
        #pragma unroll
        for (int i = 0; i < 3; i++) {
            uint4 ou;
            uint32_t* ow = reinterpret_cast<uint32_t*>(&ou);
            #pragma unroll
            for (int p = 0; p < 4; p++) {
                float o0 = a[i][0] * vf[0][2*p]   + a[i][1] * vf[1][2*p]   + a[i][2] * vf[2][2*p];
                float o1 = a[i][0] * vf[0][2*p+1] + a[i][1] * vf[1][2*p+1] + a[i][2] * vf[2][2*p+1];
                o0 *= 1.0f / (1.0f + __expf(-gf[i][2*p]));
                o1 *= 1.0f / (1.0f + __expf(-gf[i][2*p+1]));
                ow[p] = pack_bf16x2(o0, o1);
            }
            *reinterpret_cast<uint4*>(&g_hout[obase + (size_t)i * D3C + c * 8]) = ou;
        }
    }
}

// ---------------------------------------------------------------------------
// Launch
// ---------------------------------------------------------------------------
extern "C" void kernel_launch(void* const* d_in, const int* in_sizes, int n_in,
                              void* d_out, int out_size) {
    const float* x    = (const float*)d_in[0];
    const float* ln_g = (const float*)d_in[1];
    const float* ln_b = (const float*)d_in[2];
    const float* Wq   = (const float*)d_in[3];
    const float* bq   = (const float*)d_in[4];
    const float* Wk   = (const float*)d_in[5];
    const float* bk   = (const float*)d_in[6];
    const float* Wv   = (const float*)d_in[7];
    const float* bv   = (const float*)d_in[8];
    const float* Wg   = (const float*)d_in[9];
    const float* bg   = (const float*)d_in[10];
    const float* Wo   = (const float*)d_in[11];
    const float* bo   = (const float*)d_in[12];
    const float* gsc  = (const float*)d_in[13];
    float* out = (float*)d_out;

    uint32_t *p_xn, *p_wt;
    __nv_bfloat16 *p_proj, *p_hout;
    cudaGetSymbolAddress((void**)&p_xn,   g_xn);
    cudaGetSymbolAddress((void**)&p_proj, g_proj);
    cudaGetSymbolAddress((void**)&p_hout, g_hout);
    cudaGetSymbolAddress((void**)&p_wt,   g_wt);

    const int SMEM_BYTES = NSTG * SSW * 4;   // 165888
    cudaFuncSetAttribute((const void*)mma_gemm<D3C, false, true>,
                         cudaFuncAttributeMaxDynamicSharedMemorySize, SMEM_BYTES);
    cudaFuncSetAttribute((const void*)mma_gemm<DMOD, true, false>,
                         cudaFuncAttributeMaxDynamicSharedMemorySize, SMEM_BYTES);
    cudaFuncSetAttribute((const void*)attn_kernel,
                         cudaFuncAttributeMaxDynamicSharedMemorySize, ASMEM);

    // 1) LayerNorm + weight prep
    ln_kernel<<<NTOK, 288>>>(x, ln_g, ln_b, p_xn);
    prep_w<<<296, 256>>>(Wq, Wk, Wv, Wg, Wo);

    // 2) Four projection GEMMs (grid.z): [49152,384] @ [384,384]^T -> bf16
    {
        GemmPtrs gp;
        gp.bias[0] = bq; gp.bias[1] = bk; gp.bias[2] = bv; gp.bias[3] = bg;
        for (int zz = 0; zz < 4; zz++) {
            gp.C[zz] = p_proj + (size_t)zz * ROWS3 * D3C;
            gp.W[zz] = p_wt + (size_t)zz * (W4SZ / 2);
        }
        gp.resid = nullptr; gp.g = nullptr;
        dim3 grid(D3C / 128, ROWS3 / 256, 4);
        mma_gemm<D3C, false, true><<<grid, 256, SMEM_BYTES>>>(p_xn, gp, D3C);
    }

    // 3) Attention + gate (smem-staged)
    attn_kernel<<<NTOK / ATOK, 128, ASMEM>>>();

    // 4) Output GEMM + bias + residual*g -> fp32
    {
        GemmPtrs gp;
        gp.bias[0] = bo; gp.C[0] = out; gp.W[0] = p_wt + WO_OFF / 2;
        gp.bias[1] = gp.bias[2] = gp.bias[3] = nullptr;
        gp.C[1] = gp.C[2] = gp.C[3] = nullptr;
        gp.W[1] = gp.W[2] = gp.W[3] = nullptr;
        gp.resid = x; gp.g = gsc;
        dim3 grid(DMOD / 128, NTOK / 256, 1);
        mma_gemm<DMOD, true, false><<<grid, 256, SMEM_BYTES>>>(
            reinterpret_cast<const uint32_t*>(p_hout), gp, DMOD);
    }
}

// round 15
// speedup vs baseline: 1.0205x; 1.0205x over previous
#include <cuda_runtime.h>
#include <cuda_bf16.h>
#include <cstdint>
#include <math.h>

// ---------------------------------------------------------------------------
// Problem constants
// ---------------------------------------------------------------------------
#define NTOK   16384          // B*L
#define DMOD   1152           // D
#define D3C    384            // D/3
#define NHEAD  16
#define DK3C   24
#define ROWS3  (NTOK * 3)     // 49152
#define SCORE_SCALE 0.1178511301977579f   // 1/sqrt(72)

#define W4SZ   (D3C * D3C)
#define WOSZ   (DMOD * DMOD)
#define WO_OFF (4 * W4SZ)
#define WT_WORDS ((WO_OFF + WOSZ) / 2)

// ---------------------------------------------------------------------------
// Scratch
// ---------------------------------------------------------------------------
__device__ __align__(16) uint32_t g_xn[NTOK * DMOD / 2];          // LN out, bf16x2
__device__ __align__(16) __nv_bfloat16 g_proj[4][ROWS3 * D3C];    // q,k,v,gate bf16
__device__ __align__(16) __nv_bfloat16 g_hout[NTOK * DMOD];       // attn out, bf16
__device__ __align__(16) uint32_t g_wt[WT_WORDS];                 // weights, bf16x2

// ---------------------------------------------------------------------------
// Helpers
// ---------------------------------------------------------------------------
__device__ __forceinline__ uint32_t pack_bf16x2(float lo, float hi) {
    uint32_t r;
    asm("cvt.rn.bf16x2.f32 %0, %1, %2;" : "=r"(r) : "f"(hi), "f"(lo));
    return r;
}
__device__ __forceinline__ uint32_t smem_u32(const void* p) {
    uint32_t a;
    asm("{ .reg .u64 t; cvta.to.shared.u64 t, %1; cvt.u32.u64 %0, t; }" : "=r"(a) : "l"(p));
    return a;
}
__device__ __forceinline__ void cp_async16(uint32_t dst, const void* src) {
    asm volatile("cp.async.cg.shared.global [%0], [%1], 16;" :: "r"(dst), "l"(src));
}
__device__ __forceinline__ void cp_commit() {
    asm volatile("cp.async.commit_group;" ::: "memory");
}
template<int N>
__device__ __forceinline__ void cp_wait() {
    asm volatile("cp.async.wait_group %0;" :: "n"(N) : "memory");
}
__device__ __forceinline__ void mma_bf16(float* d, const uint32_t* a, const uint32_t* b) {
    asm volatile(
        "mma.sync.aligned.m16n8k16.row.col.f32.bf16.bf16.f32 "
        "{%0,%1,%2,%3}, {%4,%5,%6,%7}, {%8,%9}, {%0,%1,%2,%3};"
        : "+f"(d[0]), "+f"(d[1]), "+f"(d[2]), "+f"(d[3])
        : "r"(a[0]), "r"(a[1]), "r"(a[2]), "r"(a[3]), "r"(b[0]), "r"(b[1]));
}
__device__ __forceinline__ void ldmatrix_x4(uint32_t* r, uint32_t addr) {
    asm volatile("ldmatrix.sync.aligned.m8n8.x4.shared.b16 {%0,%1,%2,%3}, [%4];"
        : "=r"(r[0]), "=r"(r[1]), "=r"(r[2]), "=r"(r[3]) : "r"(addr));
}
__device__ __forceinline__ void bf8_to_f(const uint4& u, float* f) {
    const __nv_bfloat162* p = reinterpret_cast<const __nv_bfloat162*>(&u);
    #pragma unroll
    for (int i = 0; i < 4; i++) {
        float2 v = __bfloat1622float2(p[i]);
        f[2 * i] = v.x; f[2 * i + 1] = v.y;
    }
}

// ---------------------------------------------------------------------------
// Kernel 1 (merged): blocks [0, NTOK) do LayerNorm; blocks [NTOK, NTOK+296)
// convert weights to bf16x2.  Both memory-bound; prep hides inside LN.
// ---------------------------------------------------------------------------
#define PREPB 296

__global__ void ln_prep_kernel(const float* __restrict__ x,
                               const float* __restrict__ gamma,
                               const float* __restrict__ beta,
                               uint32_t* __restrict__ xn,
                               const float* __restrict__ Wq, const float* __restrict__ Wk,
                               const float* __restrict__ Wv, const float* __restrict__ Wg,
                               const float* __restrict__ Wo) {
    const int t = threadIdx.x;
    if (blockIdx.x >= NTOK) {
        // ---- weight prep ----
        const int pb = blockIdx.x - NTOK;
        for (int i = pb * blockDim.x + t; i < WT_WORDS; i += PREPB * blockDim.x) {
            float lo, hi;
            if (i < WO_OFF / 2) {
                const int z = i / (W4SZ / 2), r = i % (W4SZ / 2);
                const float* W = (z == 0) ? Wq : (z == 1) ? Wk : (z == 2) ? Wv : Wg;
                lo = W[2 * r]; hi = W[2 * r + 1];
            } else {
                const int j = i - WO_OFF / 2;
                lo = Wo[2 * j]; hi = Wo[2 * j + 1];
            }
            g_wt[i] = pack_bf16x2(lo, hi);
        }
        return;
    }
    // ---- LayerNorm ----
    const int n = blockIdx.x;
    const float4* xr = reinterpret_cast<const float4*>(x + (size_t)n * DMOD);
    float4 v = xr[t];
    float s  = v.x + v.y + v.z + v.w;
    float ss = v.x * v.x + v.y * v.y + v.z * v.z + v.w * v.w;
    #pragma unroll
    for (int off = 16; off > 0; off >>= 1) {
        s  += __shfl_xor_sync(0xffffffffu, s,  off);
        ss += __shfl_xor_sync(0xffffffffu, ss, off);
    }
    __shared__ float red_s[9], red_ss[9], stat[2];
    const int warp = t >> 5, lane = t & 31;
    if (lane == 0) { red_s[warp] = s; red_ss[warp] = ss; }
    __syncthreads();
    if (t == 0) {
        float ts = 0.f, tss = 0.f;
        #pragma unroll
        for (int i = 0; i < 9; i++) { ts += red_s[i]; tss += red_ss[i]; }
        float mu  = ts * (1.0f / DMOD);
        float var = tss * (1.0f / DMOD) - mu * mu;
        stat[0] = mu; stat[1] = rsqrtf(var + 1e-6f);
    }
    __syncthreads();
    const float mu = stat[0], rstd = stat[1];
    const float4 gm = reinterpret_cast<const float4*>(gamma)[t];
    const float4 be = reinterpret_cast<const float4*>(beta)[t];
    uint2 o;
    o.x = pack_bf16x2((v.x - mu) * rstd * gm.x + be.x, (v.y - mu) * rstd * gm.y + be.y);
    o.y = pack_bf16x2((v.z - mu) * rstd * gm.z + be.z, (v.w - mu) * rstd * gm.w + be.w);
    reinterpret_cast<uint2*>(xn + (size_t)n * (DMOD / 2))[t] = o;
}

// ---------------------------------------------------------------------------
// bf16 mma.sync GEMM with ldmatrix.  Block 256x128, 8 warps, warp 64x64.
// K-chunk = 64, 3-stage cp.async pipeline, one barrier per 64-K.
// (unchanged from the validated 510us round-11 kernel)
// ---------------------------------------------------------------------------
struct GemmPtrs {
    const float*    bias[4];
    void*           C[4];
    const uint32_t* W[4];
    const float*    resid;
    const float*    g;
};

#define PITCH  36                 // u32 words per smem row (32 data + 4 pad)
#define LROWS  384
#define SSW    (LROWS * PITCH)    // 13824
#define NSTG   3

template<int KD, bool RES, bool OUTB>
__global__ __launch_bounds__(256)
void mma_gemm(const uint32_t* __restrict__ A, GemmPtrs gp, int Ntot) {
    constexpr int KW = KD / 2;
    constexpr int NC = KD / 64;
    extern __shared__ uint32_t sm[];

    const int tid  = threadIdx.x;
    const int wid  = tid >> 5;
    const int lane = tid & 31;
    const int g    = lane >> 2;
    const int t4   = lane & 3;
    const int wm0  = (wid >> 1) * 64;
    const int wn0  = (wid & 1) * 64;
    const int z    = blockIdx.z;

    const uint32_t* W    = gp.W[z];
    const float*    bias = gp.bias[z];
    const int bm = blockIdx.y * 256;
    const int bn = blockIdx.x * 128;

    const uint32_t smaddr = smem_u32(sm);

    uint32_t adrA[4];
    #pragma unroll
    for (int ms = 0; ms < 4; ms++) {
        const int row = wm0 + ms * 16 + (lane & 15);
        const int wof = ((lane >> 4) & 1) * 4;
        adrA[ms] = (uint32_t)(row * PITCH + wof) * 4u;
    }
    uint32_t adrB[4];
    #pragma unroll
    for (int ps = 0; ps < 4; ps++) {
        const int row = wn0 + ps * 16 + (lane & 7) + ((lane >> 4) & 1) * 8;
        const int wof = ((lane >> 3) & 1) * 4;
        adrB[ps] = (uint32_t)(256 * PITCH + row * PITCH + wof) * 4u;
    }

    auto load_stage = [&](int c, int slot) {
        const int k0 = c * 32;
        const uint32_t sb = smaddr + (uint32_t)(slot * SSW) * 4u;
        #pragma unroll
        for (int t = 0; t < 12; t++) {
            const int idx = tid + t * 256;
            const int row = idx >> 3;
            const int q   = idx & 7;
            const uint32_t* src = (row < 256)
                ? (A + (size_t)(bm + row) * KW + k0 + q * 4)
                : (W + (size_t)(bn + row - 256) * KW + k0 + q * 4);
            cp_async16(sb + (uint32_t)(row * PITCH + q * 4) * 4u, src);
        }
        cp_commit();
    };

    float acc[4][8][4];
    #pragma unroll
    for (int i = 0; i < 4; i++)
        #pragma unroll
        for (int j = 0; j < 8; j++)
            #pragma unroll
            for (int r = 0; r < 4; r++) acc[i][j][r] = 0.f;

    load_stage(0, 0);
    load_stage(1, 1);

    int cslot = 0;
    int lslot = 2;
    for (int c = 0; c < NC; c++) {
        if (c < NC - 1) cp_wait<1>(); else cp_wait<0>();
        __syncthreads();
        if (c + 2 < NC) {
            load_stage(c + 2, lslot);
            if (++lslot == NSTG) lslot = 0;
        }

        const uint32_t sbase = smaddr + (uint32_t)(cslot * SSW) * 4u;
        if (++cslot == NSTG) cslot = 0;

        #pragma unroll
        for (int u = 0; u < 4; u++) {
            const uint32_t hbase = sbase + u * 32u;
            uint32_t afr[4][4];
            #pragma unroll
            for (int ms = 0; ms < 4; ms++)
                ldmatrix_x4(afr[ms], hbase + adrA[ms]);
            #pragma unroll
            for (int ps = 0; ps < 4; ps++) {
                uint32_t bfr[4];
                ldmatrix_x4(bfr, hbase + adrB[ps]);
                #pragma unroll
                for (int ms = 0; ms < 4; ms++) {
                    mma_bf16(acc[ms][2 * ps],     afr[ms], bfr);
                    mma_bf16(acc[ms][2 * ps + 1], afr[ms], bfr + 2);
                }
            }
        }
    }

    const float gval = RES ? __ldg(gp.g) : 0.f;
    #pragma unroll
    for (int ms = 0; ms < 4; ms++) {
        const int row0 = bm + wm0 + ms * 16 + g;
        #pragma unroll
        for (int ns = 0; ns < 8; ns++) {
            const int col = bn + wn0 + ns * 8 + 2 * t4;
            const float b0 = __ldg(bias + col);
            const float b1 = __ldg(bias + col + 1);
            float o0 = acc[ms][ns][0] + b0;
            float o1 = acc[ms][ns][1] + b1;
            float o2 = acc[ms][ns][2] + b0;
            float o3 = acc[ms][ns][3] + b1;
            if (RES) {
                const float* r0 = gp.resid + (size_t)row0 * Ntot + col;
                const float* r1 = gp.resid + (size_t)(row0 + 8) * Ntot + col;
                o0 = fmaf(r0[0], gval, o0);
                o1 = fmaf(r0[1], gval, o1);
                o2 = fmaf(r1[0], gval, o2);
                o3 = fmaf(r1[1], gval, o3);
            }
            if (OUTB) {
                uint32_t* Cw = (uint32_t*)gp.C[z];
                Cw[(size_t)row0 * (Ntot / 2) + (col >> 1)]       = pack_bf16x2(o0, o1);
                Cw[(size_t)(row0 + 8) * (Ntot / 2) + (col >> 1)] = pack_bf16x2(o2, o3);
            } else {
                float* C = (float*)gp.C[z];
                *reinterpret_cast<float2*>(C + (size_t)row0 * Ntot + col)       = make_float2(o0, o1);
                *reinterpret_cast<float2*>(C + (size_t)(row0 + 8) * Ntot + col) = make_float2(o2, o3);
            }
        }
    }
}

// ---------------------------------------------------------------------------
// Attention + gate: one thread per (token, head).
// EXACT round-10 configuration (best measured: 44.4us).
// ---------------------------------------------------------------------------
__global__ void attn_kernel() {
    const int t = blockIdx.x * blockDim.x + threadIdx.x;
    const int n = t >> 4;
    const int h = t & 15;
    const size_t ebase = (size_t)n * 3 * D3C + h * DK3C;

    const uint4* q4 = reinterpret_cast<const uint4*>(&g_proj[0][ebase]);
    const uint4* k4 = reinterpret_cast<const uint4*>(&g_proj[1][ebase]);
    const uint4* v4 = reinterpret_cast<const uint4*>(&g_proj[2][ebase]);
    const uint4* g4 = reinterpret_cast<const uint4*>(&g_proj[3][ebase]);

    float s[3][3] = {{0.f,0.f,0.f},{0.f,0.f,0.f},{0.f,0.f,0.f}};
    #pragma unroll
    for (int c = 0; c < 3; c++) {
        float qf[3][8], kf[3][8];
        #pragma unroll
        for (int i = 0; i < 3; i++) {
            bf8_to_f(q4[i * 48 + c], qf[i]);
            bf8_to_f(k4[i * 48 + c], kf[i]);
        }
        #pragma unroll
        for (int i = 0; i < 3; i++)
            #pragma unroll
            for (int j = 0; j < 3; j++) {
                float p = 0.f;
                #pragma unroll
                for (int d = 0; d < 8; d++) p = fmaf(qf[i][d], kf[j][d], p);
                s[i][j] += p;
            }
    }

    float a[3][3];
    #pragma unroll
    for (int i = 0; i < 3; i++) {
        float s0 = s[i][0] * SCORE_SCALE, s1 = s[i][1] * SCORE_SCALE, s2 = s[i][2] * SCORE_SCALE;
        float m = fmaxf(s0, fmaxf(s1, s2));
        float e0 = expf(s0 - m), e1 = expf(s1 - m), e2 = expf(s2 - m);
        float inv = 1.0f / (e0 + e1 + e2);
        a[i][0] = e0 * inv; a[i][1] = e1 * inv; a[i][2] = e2 * inv;
    }

    const size_t obase = (size_t)n * DMOD + h * DK3C;
    #pragma unroll
    for (int c = 0; c < 3; c++) {
        float vf[3][8], gf[3][8];
        #pragma unroll
        for (int j = 0; j < 3; j++) bf8_to_f(v4[j * 48 + c], vf[j]);
        #pragma unroll
        for (int i = 0; i < 3; i++) bf8_to_f(g4[i * 48 + c], gf[i]);
        #pragma unroll
        for (int i = 0; i < 3; i++) {
            uint4 ou;
            uint32_t* ow = reinterpret_cast<uint32_t*>(&ou);
            #pragma unroll
            for (int p = 0; p < 4; p++) {
                float o0 = a[i][0] * vf[0][2*p]   + a[i][1] * vf[1][2*p]   + a[i][2] * vf[2][2*p];
                float o1 = a[i][0] * vf[0][2*p+1] + a[i][1] * vf[1][2*p+1] + a[i][2] * vf[2][2*p+1];
                o0 *= 1.0f / (1.0f + expf(-gf[i][2*p]));
                o1 *= 1.0f / (1.0f + expf(-gf[i][2*p+1]));
                ow[p] = pack_bf16x2(o0, o1);
            }
            *reinterpret_cast<uint4*>(&g_hout[obase + (size_t)i * D3C + c * 8]) = ou;
        }
    }
}

// ---------------------------------------------------------------------------
// Launch
// ---------------------------------------------------------------------------
extern "C" void kernel_launch(void* const* d_in, const int* in_sizes, int n_in,
                              void* d_out, int out_size) {
    const float* x    = (const float*)d_in[0];
    const float* ln_g = (const float*)d_in[1];
    const float* ln_b = (const float*)d_in[2];
    const float* Wq   = (const float*)d_in[3];
    const float* bq   = (const float*)d_in[4];
    const float* Wk   = (const float*)d_in[5];
    const float* bk   = (const float*)d_in[6];
    const float* Wv   = (const float*)d_in[7];
    const float* bv   = (const float*)d_in[8];
    const float* Wg   = (const float*)d_in[9];
    const float* bg   = (const float*)d_in[10];
    const float* Wo   = (const float*)d_in[11];
    const float* bo   = (const float*)d_in[12];
    const float* gsc  = (const float*)d_in[13];
    float* out = (float*)d_out;

    uint32_t *p_xn, *p_wt;
    __nv_bfloat16 *p_proj, *p_hout;
    cudaGetSymbolAddress((void**)&p_xn,   g_xn);
    cudaGetSymbolAddress((void**)&p_proj, g_proj);
    cudaGetSymbolAddress((void**)&p_hout, g_hout);
    cudaGetSymbolAddress((void**)&p_wt,   g_wt);

    const int SMEM_BYTES = NSTG * SSW * 4;   // 165888
    cudaFuncSetAttribute((const void*)mma_gemm<D3C, false, true>,
                         cudaFuncAttributeMaxDynamicSharedMemorySize, SMEM_BYTES);
    cudaFuncSetAttribute((const void*)mma_gemm<DMOD, true, false>,
                         cudaFuncAttributeMaxDynamicSharedMemorySize, SMEM_BYTES);

    // 1) LayerNorm + weight prep (merged single launch)
    ln_prep_kernel<<<NTOK + PREPB, 288>>>(x, ln_g, ln_b, p_xn, Wq, Wk, Wv, Wg, Wo);

    // 2) Four projection GEMMs (grid.z): [49152,384] @ [384,384]^T -> bf16
    {
        GemmPtrs gp;
        gp.bias[0] = bq; gp.bias[1] = bk; gp.bias[2] = bv; gp.bias[3] = bg;
        for (int zz = 0; zz < 4; zz++) {
            gp.C[zz] = p_proj + (size_t)zz * ROWS3 * D3C;
            gp.W[zz] = p_wt + (size_t)zz * (W4SZ / 2);
        }
        gp.resid = nullptr; gp.g = nullptr;
        dim3 grid(D3C / 128, ROWS3 / 256, 4);
        mma_gemm<D3C, false, true><<<grid, 256, SMEM_BYTES>>>(p_xn, gp, D3C);
    }

    // 3) Attention + gate
    attn_kernel<<<NTOK * NHEAD / 256, 256>>>();

    // 4) Output GEMM + bias + residual*g -> fp32
    {
        GemmPtrs gp;
        gp.bias[0] = bo; gp.C[0] = out; gp.W[0] = p_wt + WO_OFF / 2;
        gp.bias[1] = gp.bias[2] = gp.bias[3] = nullptr;
        gp.C[1] = gp.C[2] = gp.C[3] = nullptr;
        gp.W[1] = gp.W[2] = gp.W[3] = nullptr;
        gp.resid = x; gp.g = gsc;
        dim3 grid(DMOD / 128, NTOK / 256, 1);
        mma_gemm<DMOD, true, false><<<grid, 256, SMEM_BYTES>>>(
            reinterpret_cast<const uint32_t*>(p_hout), gp, DMOD);
    }
}

// round 17
// speedup vs baseline: 1.0864x; 1.0646x over previous
#include <cuda_runtime.h>
#include <cuda_bf16.h>
#include <cstdint>
#include <math.h>

// ---------------------------------------------------------------------------
// Problem constants
// ---------------------------------------------------------------------------
#define NTOK   16384          // B*L
#define DMOD   1152           // D
#define D3C    384            // D/3
#define NHEAD  16
#define DK3C   24
#define ROWS3  (NTOK * 3)     // 49152
#define SCORE_SCALE 0.1178511301977579f   // 1/sqrt(72)

#define W4SZ   (D3C * D3C)
#define WOSZ   (DMOD * DMOD)
#define WO_OFF (4 * W4SZ)
#define WT_WORDS ((WO_OFF + WOSZ) / 2)

// ---------------------------------------------------------------------------
// Scratch
// ---------------------------------------------------------------------------
__device__ __align__(16) uint32_t g_xn[NTOK * DMOD / 2];          // LN out, bf16x2
__device__ __align__(16) __nv_bfloat16 g_proj[4][ROWS3 * D3C];    // q,k,v,gate bf16
__device__ __align__(16) __nv_bfloat16 g_hout[NTOK * DMOD];       // attn out, bf16
__device__ __align__(16) uint32_t g_wt[WT_WORDS];                 // weights, bf16x2

// ---------------------------------------------------------------------------
// Helpers
// ---------------------------------------------------------------------------
__device__ __forceinline__ uint32_t pack_bf16x2(float lo, float hi) {
    uint32_t r;
    asm("cvt.rn.bf16x2.f32 %0, %1, %2;" : "=r"(r) : "f"(hi), "f"(lo));
    return r;
}
__device__ __forceinline__ uint32_t smem_u32(const void* p) {
    uint32_t a;
    asm("{ .reg .u64 t; cvta.to.shared.u64 t, %1; cvt.u32.u64 %0, t; }" : "=r"(a) : "l"(p));
    return a;
}
__device__ __forceinline__ void cp_async16(uint32_t dst, const void* src) {
    asm volatile("cp.async.cg.shared.global [%0], [%1], 16;" :: "r"(dst), "l"(src));
}
__device__ __forceinline__ void cp_commit() {
    asm volatile("cp.async.commit_group;" ::: "memory");
}
template<int N>
__device__ __forceinline__ void cp_wait() {
    asm volatile("cp.async.wait_group %0;" :: "n"(N) : "memory");
}
__device__ __forceinline__ void mma_bf16(float* d, const uint32_t* a, const uint32_t* b) {
    asm volatile(
        "mma.sync.aligned.m16n8k16.row.col.f32.bf16.bf16.f32 "
        "{%0,%1,%2,%3}, {%4,%5,%6,%7}, {%8,%9}, {%0,%1,%2,%3};"
        : "+f"(d[0]), "+f"(d[1]), "+f"(d[2]), "+f"(d[3])
        : "r"(a[0]), "r"(a[1]), "r"(a[2]), "r"(a[3]), "r"(b[0]), "r"(b[1]));
}
__device__ __forceinline__ void ldmatrix_x4(uint32_t* r, uint32_t addr) {
    asm volatile("ldmatrix.sync.aligned.m8n8.x4.shared.b16 {%0,%1,%2,%3}, [%4];"
        : "=r"(r[0]), "=r"(r[1]), "=r"(r[2]), "=r"(r[3]) : "r"(addr));
}
__device__ __forceinline__ void bf8_to_f(const uint4& u, float* f) {
    const __nv_bfloat162* p = reinterpret_cast<const __nv_bfloat162*>(&u);
    #pragma unroll
    for (int i = 0; i < 4; i++) {
        float2 v = __bfloat1622float2(p[i]);
        f[2 * i] = v.x; f[2 * i + 1] = v.y;
    }
}

// ---------------------------------------------------------------------------
// Kernel 1 (merged): blocks [0, NTOK) LayerNorm; [NTOK, NTOK+296) weight prep.
// ---------------------------------------------------------------------------
#define PREPB 296

__global__ void ln_prep_kernel(const float* __restrict__ x,
                               const float* __restrict__ gamma,
                               const float* __restrict__ beta,
                               uint32_t* __restrict__ xn,
                               const float* __restrict__ Wq, const float* __restrict__ Wk,
                               const float* __restrict__ Wv, const float* __restrict__ Wg,
                               const float* __restrict__ Wo) {
    const int t = threadIdx.x;
    if (blockIdx.x >= NTOK) {
        const int pb = blockIdx.x - NTOK;
        for (int i = pb * blockDim.x + t; i < WT_WORDS; i += PREPB * blockDim.x) {
            float lo, hi;
            if (i < WO_OFF / 2) {
                const int z = i / (W4SZ / 2), r = i % (W4SZ / 2);
                const float* W = (z == 0) ? Wq : (z == 1) ? Wk : (z == 2) ? Wv : Wg;
                lo = W[2 * r]; hi = W[2 * r + 1];
            } else {
                const int j = i - WO_OFF / 2;
                lo = Wo[2 * j]; hi = Wo[2 * j + 1];
            }
            g_wt[i] = pack_bf16x2(lo, hi);
        }
        return;
    }
    const int n = blockIdx.x;
    const float4* xr = reinterpret_cast<const float4*>(x + (size_t)n * DMOD);
    float4 v = xr[t];
    float s  = v.x + v.y + v.z + v.w;
    float ss = v.x * v.x + v.y * v.y + v.z * v.z + v.w * v.w;
    #pragma unroll
    for (int off = 16; off > 0; off >>= 1) {
        s  += __shfl_xor_sync(0xffffffffu, s,  off);
        ss += __shfl_xor_sync(0xffffffffu, ss, off);
    }
    __shared__ float red_s[9], red_ss[9], stat[2];
    const int warp = t >> 5, lane = t & 31;
    if (lane == 0) { red_s[warp] = s; red_ss[warp] = ss; }
    __syncthreads();
    if (t == 0) {
        float ts = 0.f, tss = 0.f;
        #pragma unroll
        for (int i = 0; i < 9; i++) { ts += red_s[i]; tss += red_ss[i]; }
        float mu  = ts * (1.0f / DMOD);
        float var = tss * (1.0f / DMOD) - mu * mu;
        stat[0] = mu; stat[1] = rsqrtf(var + 1e-6f);
    }
    __syncthreads();
    const float mu = stat[0], rstd = stat[1];
    const float4 gm = reinterpret_cast<const float4*>(gamma)[t];
    const float4 be = reinterpret_cast<const float4*>(beta)[t];
    uint2 o;
    o.x = pack_bf16x2((v.x - mu) * rstd * gm.x + be.x, (v.y - mu) * rstd * gm.y + be.y);
    o.y = pack_bf16x2((v.z - mu) * rstd * gm.z + be.z, (v.w - mu) * rstd * gm.w + be.w);
    reinterpret_cast<uint2*>(xn + (size_t)n * (DMOD / 2))[t] = o;
}

// ---------------------------------------------------------------------------
// bf16 mma.sync GEMM.  Block tile 128x128, 8 warps, warp tile 32x64.
// K-chunk 64, 3-stage pipeline, ~105 regs -> 2 CTAs/SM for barrier overlap.
// ---------------------------------------------------------------------------
struct GemmPtrs {
    const float*    bias[4];
    void*           C[4];
    const uint32_t* W[4];
    const float*    resid;
    const float*    g;
};

#define PITCH  36                 // u32 words per smem row (32 data + 4 pad)
#define LROWS  256                // 128 A rows + 128 B rows per stage
#define SSW    (LROWS * PITCH)    // 9216 u32 words per stage
#define NSTG   3

template<int KD, bool RES, bool OUTB>
__global__ __launch_bounds__(256, 2)
void mma_gemm(const uint32_t* __restrict__ A, GemmPtrs gp, int Ntot) {
    constexpr int KW = KD / 2;
    constexpr int NC = KD / 64;
    extern __shared__ uint32_t sm[];

    const int tid  = threadIdx.x;
    const int wid  = tid >> 5;
    const int lane = tid & 31;
    const int g    = lane >> 2;
    const int t4   = lane & 3;
    const int wm0  = (wid >> 1) * 32;      // 4 warps along M: 0,32,64,96
    const int wn0  = (wid & 1) * 64;       // 2 warps along N: 0,64
    const int z    = blockIdx.z;

    const uint32_t* W    = gp.W[z];
    const float*    bias = gp.bias[z];
    const int bm = blockIdx.y * 128;
    const int bn = blockIdx.x * 128;

    const uint32_t smaddr = smem_u32(sm);

    uint32_t adrA[2];
    #pragma unroll
    for (int ms = 0; ms < 2; ms++) {
        const int row = wm0 + ms * 16 + (lane & 15);
        const int wof = ((lane >> 4) & 1) * 4;
        adrA[ms] = (uint32_t)(row * PITCH + wof) * 4u;
    }
    uint32_t adrB[4];
    #pragma unroll
    for (int ps = 0; ps < 4; ps++) {
        const int row = wn0 + ps * 16 + (lane & 7) + ((lane >> 4) & 1) * 8;
        const int wof = ((lane >> 3) & 1) * 4;
        adrB[ps] = (uint32_t)(128 * PITCH + row * PITCH + wof) * 4u;
    }

    // Load one 64-K chunk: 256 rows x 32 words; 8 cp.async16 per thread.
    auto load_stage = [&](int c, int slot) {
        const int k0 = c * 32;
        const uint32_t sb = smaddr + (uint32_t)(slot * SSW) * 4u;
        #pragma unroll
        for (int t = 0; t < 8; t++) {
            const int idx = tid + t * 256;     // 0..2047
            const int row = idx >> 3;          // 0..255
            const int q   = idx & 7;
            const uint32_t* src = (row < 128)
                ? (A + (size_t)(bm + row) * KW + k0 + q * 4)
                : (W + (size_t)(bn + row - 128) * KW + k0 + q * 4);
            cp_async16(sb + (uint32_t)(row * PITCH + q * 4) * 4u, src);
        }
        cp_commit();
    };

    float acc[2][8][4];
    #pragma unroll
    for (int i = 0; i < 2; i++)
        #pragma unroll
        for (int j = 0; j < 8; j++)
            #pragma unroll
            for (int r = 0; r < 4; r++) acc[i][j][r] = 0.f;

    load_stage(0, 0);
    load_stage(1, 1);

    int cslot = 0;
    int lslot = 2;
    for (int c = 0; c < NC; c++) {
        if (c < NC - 1) cp_wait<1>(); else cp_wait<0>();
        __syncthreads();
        if (c + 2 < NC) {
            load_stage(c + 2, lslot);
            if (++lslot == NSTG) lslot = 0;
        }

        const uint32_t sbase = smaddr + (uint32_t)(cslot * SSW) * 4u;
        if (++cslot == NSTG) cslot = 0;

        #pragma unroll
        for (int u = 0; u < 4; u++) {          // four 16-K halves of the chunk
            const uint32_t hbase = sbase + u * 32u;
            uint32_t afr[2][4];
            #pragma unroll
            for (int ms = 0; ms < 2; ms++)
                ldmatrix_x4(afr[ms], hbase + adrA[ms]);
            #pragma unroll
            for (int ps = 0; ps < 4; ps++) {
                uint32_t bfr[4];
                ldmatrix_x4(bfr, hbase + adrB[ps]);
                #pragma unroll
                for (int ms = 0; ms < 2; ms++) {
                    mma_bf16(acc[ms][2 * ps],     afr[ms], bfr);
                    mma_bf16(acc[ms][2 * ps + 1], afr[ms], bfr + 2);
                }
            }
        }
    }

    // Epilogue
    const float gval = RES ? __ldg(gp.g) : 0.f;
    #pragma unroll
    for (int ms = 0; ms < 2; ms++) {
        const int row0 = bm + wm0 + ms * 16 + g;
        #pragma unroll
        for (int ns = 0; ns < 8; ns++) {
            const int col = bn + wn0 + ns * 8 + 2 * t4;
            const float b0 = __ldg(bias + col);
            const float b1 = __ldg(bias + col + 1);
            float o0 = acc[ms][ns][0] + b0;
            float o1 = acc[ms][ns][1] + b1;
            float o2 = acc[ms][ns][2] + b0;
            float o3 = acc[ms][ns][3] + b1;
            if (RES) {
                const float* r0 = gp.resid + (size_t)row0 * Ntot + col;
                const float* r1 = gp.resid + (size_t)(row0 + 8) * Ntot + col;
                o0 = fmaf(r0[0], gval, o0);
                o1 = fmaf(r0[1], gval, o1);
                o2 = fmaf(r1[0], gval, o2);
                o3 = fmaf(r1[1], gval, o3);
            }
            if (OUTB) {
                uint32_t* Cw = (uint32_t*)gp.C[z];
                Cw[(size_t)row0 * (Ntot / 2) + (col >> 1)]       = pack_bf16x2(o0, o1);
                Cw[(size_t)(row0 + 8) * (Ntot / 2) + (col >> 1)] = pack_bf16x2(o2, o3);
            } else {
                float* C = (float*)gp.C[z];
                *reinterpret_cast<float2*>(C + (size_t)row0 * Ntot + col)       = make_float2(o0, o1);
                *reinterpret_cast<float2*>(C + (size_t)(row0 + 8) * Ntot + col) = make_float2(o2, o3);
            }
        }
    }
}

// ---------------------------------------------------------------------------
// Attention + gate: one thread per (token, head) (validated round-10 config)
// ---------------------------------------------------------------------------
__global__ void attn_kernel() {
    const int t = blockIdx.x * blockDim.x + threadIdx.x;
    const int n = t >> 4;
    const int h = t & 15;
    const size_t ebase = (size_t)n * 3 * D3C + h * DK3C;

    const uint4* q4 = reinterpret_cast<const uint4*>(&g_proj[0][ebase]);
    const uint4* k4 = reinterpret_cast<const uint4*>(&g_proj[1][ebase]);
    const uint4* v4 = reinterpret_cast<const uint4*>(&g_proj[2][ebase]);
    const uint4* g4 = reinterpret_cast<const uint4*>(&g_proj[3][ebase]);

    float s[3][3] = {{0.f,0.f,0.f},{0.f,0.f,0.f},{0.f,0.f,0.f}};
    #pragma unroll
    for (int c = 0; c < 3; c++) {
        float qf[3][8], kf[3][8];
        #pragma unroll
        for (int i = 0; i < 3; i++) {
            bf8_to_f(q4[i * 48 + c], qf[i]);
            bf8_to_f(k4[i * 48 + c], kf[i]);
        }
        #pragma unroll
        for (int i = 0; i < 3; i++)
            #pragma unroll
            for (int j = 0; j < 3; j++) {
                float p = 0.f;
                #pragma unroll
                for (int d = 0; d < 8; d++) p = fmaf(qf[i][d], kf[j][d], p);
                s[i][j] += p;
            }
    }

    float a[3][3];
    #pragma unroll
    for (int i = 0; i < 3; i++) {
        float s0 = s[i][0] * SCORE_SCALE, s1 = s[i][1] * SCORE_SCALE, s2 = s[i][2] * SCORE_SCALE;
        float m = fmaxf(s0, fmaxf(s1, s2));
        float e0 = expf(s0 - m), e1 = expf(s1 - m), e2 = expf(s2 - m);
        float inv = 1.0f / (e0 + e1 + e2);
        a[i][0] = e0 * inv; a[i][1] = e1 * inv; a[i][2] = e2 * inv;
    }

    const size_t obase = (size_t)n * DMOD + h * DK3C;
    #pragma unroll
    for (int c = 0; c < 3; c++) {
        float vf[3][8], gf[3][8];
        #pragma unroll
        for (int j = 0; j < 3; j++) bf8_to_f(v4[j * 48 + c], vf[j]);
        #pragma unroll
        for (int i = 0; i < 3; i++) bf8_to_f(g4[i * 48 + c], gf[i]);
        #pragma unroll
        for (int i = 0; i < 3; i++) {
            uint4 ou;
            uint32_t* ow = reinterpret_cast<uint32_t*>(&ou);
            #pragma unroll
            for (int p = 0; p < 4; p++) {
                float o0 = a[i][0] * vf[0][2*p]   + a[i][1] * vf[1][2*p]   + a[i][2] * vf[2][2*p];
                float o1 = a[i][0] * vf[0][2*p+1] + a[i][1] * vf[1][2*p+1] + a[i][2] * vf[2][2*p+1];
                o0 *= 1.0f / (1.0f + expf(-gf[i][2*p]));
                o1 *= 1.0f / (1.0f + expf(-gf[i][2*p+1]));
                ow[p] = pack_bf16x2(o0, o1);
            }
            *reinterpret_cast<uint4*>(&g_hout[obase + (size_t)i * D3C + c * 8]) = ou;
        }
    }
}

// ---------------------------------------------------------------------------
// Launch
// ---------------------------------------------------------------------------
extern "C" void kernel_launch(void* const* d_in, const int* in_sizes, int n_in,
                              void* d_out, int out_size) {
    const float* x    = (const float*)d_in[0];
    const float* ln_g = (const float*)d_in[1];
    const float* ln_b = (const float*)d_in[2];
    const float* Wq   = (const float*)d_in[3];
    const float* bq   = (const float*)d_in[4];
    const float* Wk   = (const float*)d_in[5];
    const float* bk   = (const float*)d_in[6];
    const float* Wv   = (const float*)d_in[7];
    const float* bv   = (const float*)d_in[8];
    const float* Wg   = (const float*)d_in[9];
    const float* bg   = (const float*)d_in[10];
    const float* Wo   = (const float*)d_in[11];
    const float* bo   = (const float*)d_in[12];
    const float* gsc  = (const float*)d_in[13];
    float* out = (float*)d_out;

    uint32_t *p_xn, *p_wt;
    __nv_bfloat16 *p_proj, *p_hout;
    cudaGetSymbolAddress((void**)&p_xn,   g_xn);
    cudaGetSymbolAddress((void**)&p_proj, g_proj);
    cudaGetSymbolAddress((void**)&p_hout, g_hout);
    cudaGetSymbolAddress((void**)&p_wt,   g_wt);

    const int SMEM_BYTES = NSTG * SSW * 4;   // 3 * 9216 * 4 = 110592
    cudaFuncSetAttribute((const void*)mma_gemm<D3C, false, true>,
                         cudaFuncAttributeMaxDynamicSharedMemorySize, SMEM_BYTES);
    cudaFuncSetAttribute((const void*)mma_gemm<DMOD, true, false>,
                         cudaFuncAttributeMaxDynamicSharedMemorySize, SMEM_BYTES);

    // 1) LayerNorm + weight prep (merged)
    ln_prep_kernel<<<NTOK + PREPB, 288>>>(x, ln_g, ln_b, p_xn, Wq, Wk, Wv, Wg, Wo);

    // 2) Four projection GEMMs (grid.z): [49152,384] @ [384,384]^T -> bf16
    {
        GemmPtrs gp;
        gp.bias[0] = bq; gp.bias[1] = bk; gp.bias[2] = bv; gp.bias[3] = bg;
        for (int zz = 0; zz < 4; zz++) {
            gp.C[zz] = p_proj + (size_t)zz * ROWS3 * D3C;
            gp.W[zz] = p_wt + (size_t)zz * (W4SZ / 2);
        }
        gp.resid = nullptr; gp.g = nullptr;
        dim3 grid(D3C / 128, ROWS3 / 128, 4);   // (3, 384, 4)
        mma_gemm<D3C, false, true><<<grid, 256, SMEM_BYTES>>>(p_xn, gp, D3C);
    }

    // 3) Attention + gate
    attn_kernel<<<NTOK * NHEAD / 256, 256>>>();

    // 4) Output GEMM + bias + residual*g -> fp32
    {
        GemmPtrs gp;
        gp.bias[0] = bo; gp.C[0] = out; gp.W[0] = p_wt + WO_OFF / 2;
        gp.bias[1] = gp.bias[2] = gp.bias[3] = nullptr;
        gp.C[1] = gp.C[2] = gp.C[3] = nullptr;
        gp.W[1] = gp.W[2] = gp.W[3] = nullptr;
        gp.resid = x; gp.g = gsc;
        dim3 grid(DMOD / 128, NTOK / 128, 1);   // (9, 128, 1)
        mma_gemm<DMOD, true, false><<<grid, 256, SMEM_BYTES>>>(
            reinterpret_cast<const uint32_t*>(p_hout), gp, DMOD);
    }
}